// round 5
// baseline (speedup 1.0000x reference)
#include <cuda_runtime.h>
#include <cuda_bf16.h>
#include <cuda_fp16.h>
#include <math.h>

// Fixed problem shape
#define BB   4
#define NN   32768
#define KK   16
#define CIN  32
#define HH   32
#define COUT 32
#define PP   3

#define GTOT (BB * NN)          // 131072 nodes
#define ETOT (BB * NN * KK)     // 2097152 edges
#define MELEMS (GTOT * HH)      // 4194304 elements

// Scratch (__device__ globals; no allocation allowed)
__device__ __half  g_mh[MELEMS];   // m[node,h] in fp16 (8 MB)
__device__ float   g_acc[MELEMS];  // segment-sum accumulator (fp32, 16 MB)
__device__ float4  g_grid4[GTOT];  // packed grid coords (x,y,z,0)

// Small weights in constant memory -> uniform LDCU path on sm_103a
__constant__ float cW1[HH * CIN];
__constant__ float cb1[HH];
__constant__ float cbw[HH];
__constant__ float cW2[COUT * HH];
__constant__ float cb2[COUT];

// ---------------------------------------------------------------------------
// gemm1 fused, 2 nodes per thread (nodes g and g+GTOT/2):
//   m_h[g,h] = half((W1x+b1)*gw*sqrt((bw/pi)^3)) ; acc[g,:]=0 ; grid4 pack.
// One LDCU per weight feeds two FFMAs.
// ---------------------------------------------------------------------------
__global__ void gemm1_kernel(const float* __restrict__ x,
                             const float* __restrict__ gw,
                             const float* __restrict__ grid) {
    int i  = blockIdx.x * blockDim.x + threadIdx.x;  // [0, GTOT/2)
    int g0 = i;
    int g1 = i + GTOT / 2;

    const float* xb0 = x + (size_t)(g0 >> 15) * CIN * NN + (g0 & (NN - 1));
    const float* xb1 = x + (size_t)(g1 >> 15) * CIN * NN + (g1 & (NN - 1));

    float a0[HH], a1[HH];
#pragma unroll
    for (int h = 0; h < HH; h++) { a0[h] = 0.f; a1[h] = 0.f; }

#pragma unroll
    for (int c = 0; c < CIN; c++) {
        float xv0 = xb0[(size_t)c * NN];             // coalesced
        float xv1 = xb1[(size_t)c * NN];             // coalesced
#pragma unroll
        for (int h = 0; h < HH; h++) {
            float w = cW1[h * CIN + c];              // LDCU, shared by both
            a0[h] += w * xv0;
            a1[h] += w * xv1;
        }
    }

    float w0 = gw[g0];
    float w1 = gw[g1];

#pragma unroll
    for (int node = 0; node < 2; node++) {
        int g = node ? g1 : g0;
        float wgt = node ? w1 : w0;
        const float* a = node ? a1 : a0;

        // 32 halves = 64 bytes = 4 x uint4  (FIX: was ov[2] -> overflow + half row lost)
        uint4 ov[4];
        unsigned int* oh = reinterpret_cast<unsigned int*>(ov);
#pragma unroll
        for (int hp = 0; hp < HH / 2; hp++) {
            int h0 = 2 * hp, h1 = 2 * hp + 1;
            float r0 = cbw[h0] * 0.3183098861837907f;
            float r1 = cbw[h1] * 0.3183098861837907f;
            float m0 = (a[h0] + cb1[h0]) * wgt * sqrtf(r0 * r0 * r0);
            float m1 = (a[h1] + cb1[h1]) * wgt * sqrtf(r1 * r1 * r1);
            __half2 h2 = __floats2half2_rn(m0, m1);
            oh[hp] = *reinterpret_cast<unsigned int*>(&h2);
        }
        uint4* mo = reinterpret_cast<uint4*>(g_mh + (size_t)g * HH);
#pragma unroll
        for (int q = 0; q < 4; q++) mo[q] = ov[q];

        float4* ao = reinterpret_cast<float4*>(g_acc + (size_t)g * HH);
#pragma unroll
        for (int j = 0; j < HH / 4; j++) ao[j] = make_float4(0.f, 0.f, 0.f, 0.f);

        const float* gp = grid + (size_t)g * PP;
        g_grid4[g] = make_float4(gp[0], gp[1], gp[2], 0.f);
    }
}

// ---------------------------------------------------------------------------
// Edge kernel: each warp owns 32 edges; two-phase.
// Phase 1 (lane = edge): coalesced index loads, float4 grid gathers, d2.
// Phase 2 (lane = channel): broadcast LDS.128, fp16 m gather (64B row),
//   EX2, RED.E.ADD.F32.
// ---------------------------------------------------------------------------
__global__ void edge_kernel(const int* __restrict__ es,
                            const int* __restrict__ ed,
                            const float* __restrict__ bw) {
    __shared__ float4 stage[8][32];                  // 8 warps/block
    int tid  = blockIdx.x * blockDim.x + threadIdx.x;
    int lane = threadIdx.x & 31;
    int w    = threadIdx.x >> 5;

    // ---- phase 1: lane = edge ----
    int e   = tid;                                   // grid sized to ETOT
    int b   = e >> 19;                               // NN*KK = 2^19
    int off = b << 15;                               // b * NN
    int s   = __ldg(es + e) + off;
    int d   = __ldg(ed + e) + off;

    float4 gs = g_grid4[s];
    float4 gd = g_grid4[d];
    float dx = gs.x - gd.x;
    float dy = gs.y - gd.y;
    float dz = gs.z - gd.z;
    float d2 = dx * dx + dy * dy + dz * dz;

    stage[w][lane] = make_float4(__int_as_float(s * HH),
                                 __int_as_float(d * HH), d2, 0.f);
    __syncwarp();

    // ---- phase 2: lane = hidden channel ----
    float nb = __ldg(bw + lane) * (-1.4426950408889634f);  // -bw*log2e

#pragma unroll 8
    for (int i = 0; i < 32; i++) {
        float4 p  = stage[w][i];                     // broadcast LDS.128
        int   si  = __float_as_int(p.x);
        int   di  = __float_as_int(p.y);
        float d2i = p.z;
        float mv  = __half2float(g_mh[si + lane]);   // 64B coalesced row
        float ex;
        asm("ex2.approx.f32 %0, %1;" : "=f"(ex) : "f"(nb * d2i));
        atomicAdd(g_acc + di + lane, mv * ex);       // RED.E.ADD.F32
    }
}

// ---------------------------------------------------------------------------
// gemm2: out[b,o,n] = sum_h W2[o,h]*acc[g,h] + b2[o]
// ---------------------------------------------------------------------------
__global__ void gemm2_kernel(float* __restrict__ out) {
    int g = blockIdx.x * blockDim.x + threadIdx.x;
    int b = g >> 15;
    int n = g & (NN - 1);

    float a[HH];
    const float4* av = reinterpret_cast<const float4*>(g_acc + (size_t)g * HH);
#pragma unroll
    for (int i = 0; i < HH / 4; i++) {
        float4 v = av[i];
        a[4 * i + 0] = v.x;
        a[4 * i + 1] = v.y;
        a[4 * i + 2] = v.z;
        a[4 * i + 3] = v.w;
    }

    float* ob = out + (size_t)b * COUT * NN + n;
#pragma unroll
    for (int o = 0; o < COUT; o++) {
        float s = cb2[o];
#pragma unroll
        for (int h = 0; h < HH; h++)
            s += cW2[o * HH + h] * a[h];             // LDCU + FFMA
        ob[(size_t)o * NN] = s;
    }
}

// ---------------------------------------------------------------------------
// Launcher
// inputs: 0:x 1:grid 2:grid_weight 3:edge_src 4:edge_dst 5:W1 6:b1 7:W2 8:b2 9:baseweight
// ---------------------------------------------------------------------------
extern "C" void kernel_launch(void* const* d_in, const int* in_sizes, int n_in,
                              void* d_out, int out_size) {
    const float* x    = (const float*)d_in[0];
    const float* grid = (const float*)d_in[1];
    const float* gw   = (const float*)d_in[2];
    const int*   es   = (const int*)d_in[3];
    const int*   ed   = (const int*)d_in[4];
    const float* W1   = (const float*)d_in[5];
    const float* b1   = (const float*)d_in[6];
    const float* W2   = (const float*)d_in[7];
    const float* b2   = (const float*)d_in[8];
    const float* bw   = (const float*)d_in[9];
    float* out = (float*)d_out;

    // Stage small weights into constant memory (D2D, graph-capturable)
    cudaMemcpyToSymbolAsync(cW1, W1, HH * CIN * sizeof(float), 0,
                            cudaMemcpyDeviceToDevice, 0);
    cudaMemcpyToSymbolAsync(cb1, b1, HH * sizeof(float), 0,
                            cudaMemcpyDeviceToDevice, 0);
    cudaMemcpyToSymbolAsync(cbw, bw, HH * sizeof(float), 0,
                            cudaMemcpyDeviceToDevice, 0);
    cudaMemcpyToSymbolAsync(cW2, W2, COUT * HH * sizeof(float), 0,
                            cudaMemcpyDeviceToDevice, 0);
    cudaMemcpyToSymbolAsync(cb2, b2, COUT * sizeof(float), 0,
                            cudaMemcpyDeviceToDevice, 0);

    // 1) fused fc1 + gauss-norm + grid_weight -> g_mh ; zero acc ; pack grid
    gemm1_kernel<<<(GTOT / 2) / 256, 256>>>(x, gw, grid);

    // 2) edge scatter: 32 edges per warp, two-phase, fp16 m gather
    edge_kernel<<<ETOT / 256, 256>>>(es, ed, bw);

    // 3) fc2 + transpose to (B, COUT, N)
    gemm2_kernel<<<GTOT / 256, 256>>>(out);
}

// round 6
// speedup vs baseline: 1.0095x; 1.0095x over previous
#include <cuda_runtime.h>
#include <cuda_bf16.h>
#include <cuda_fp16.h>
#include <math.h>

// Fixed problem shape
#define BB   4
#define NN   32768
#define KK   16
#define CIN  32
#define HH   32
#define COUT 32
#define PP   3

#define GTOT (BB * NN)          // 131072 nodes
#define ETOT (BB * NN * KK)     // 2097152 edges
#define MELEMS (GTOT * HH)      // 4194304 elements

// Scratch (__device__ globals; no allocation allowed)
__device__ __half  g_mh[MELEMS];   // m[node,h] in fp16 (8 MB)
__device__ float   g_acc[MELEMS];  // segment-sum accumulator (fp32, 16 MB)
__device__ float4  g_grid4[GTOT];  // packed grid coords (x,y,z,0)

// Small weights in constant memory -> uniform LDCU path on sm_103a
__constant__ float cW1[HH * CIN];
__constant__ float cb1[HH];
__constant__ float cbw[HH];
__constant__ float cW2[COUT * HH];
__constant__ float cb2[COUT];

// ---------------------------------------------------------------------------
// gemm1 fused, 2 nodes per thread (nodes g and g+GTOT/2)  [unchanged, passing]
// ---------------------------------------------------------------------------
__global__ void gemm1_kernel(const float* __restrict__ x,
                             const float* __restrict__ gw,
                             const float* __restrict__ grid) {
    int i  = blockIdx.x * blockDim.x + threadIdx.x;  // [0, GTOT/2)
    int g0 = i;
    int g1 = i + GTOT / 2;

    const float* xb0 = x + (size_t)(g0 >> 15) * CIN * NN + (g0 & (NN - 1));
    const float* xb1 = x + (size_t)(g1 >> 15) * CIN * NN + (g1 & (NN - 1));

    float a0[HH], a1[HH];
#pragma unroll
    for (int h = 0; h < HH; h++) { a0[h] = 0.f; a1[h] = 0.f; }

#pragma unroll
    for (int c = 0; c < CIN; c++) {
        float xv0 = xb0[(size_t)c * NN];             // coalesced
        float xv1 = xb1[(size_t)c * NN];             // coalesced
#pragma unroll
        for (int h = 0; h < HH; h++) {
            float w = cW1[h * CIN + c];              // LDCU, shared by both
            a0[h] += w * xv0;
            a1[h] += w * xv1;
        }
    }

    float w0 = gw[g0];
    float w1 = gw[g1];

#pragma unroll
    for (int node = 0; node < 2; node++) {
        int g = node ? g1 : g0;
        float wgt = node ? w1 : w0;
        const float* a = node ? a1 : a0;

        uint4 ov[4];                                 // 32 halves = 64 B
        unsigned int* oh = reinterpret_cast<unsigned int*>(ov);
#pragma unroll
        for (int hp = 0; hp < HH / 2; hp++) {
            int h0 = 2 * hp, h1 = 2 * hp + 1;
            float r0 = cbw[h0] * 0.3183098861837907f;
            float r1 = cbw[h1] * 0.3183098861837907f;
            float m0 = (a[h0] + cb1[h0]) * wgt * sqrtf(r0 * r0 * r0);
            float m1 = (a[h1] + cb1[h1]) * wgt * sqrtf(r1 * r1 * r1);
            __half2 h2 = __floats2half2_rn(m0, m1);
            oh[hp] = *reinterpret_cast<unsigned int*>(&h2);
        }
        uint4* mo = reinterpret_cast<uint4*>(g_mh + (size_t)g * HH);
#pragma unroll
        for (int q = 0; q < 4; q++) mo[q] = ov[q];

        float4* ao = reinterpret_cast<float4*>(g_acc + (size_t)g * HH);
#pragma unroll
        for (int j = 0; j < HH / 4; j++) ao[j] = make_float4(0.f, 0.f, 0.f, 0.f);

        const float* gp = grid + (size_t)g * PP;
        g_grid4[g] = make_float4(gp[0], gp[1], gp[2], 0.f);
    }
}

// ---------------------------------------------------------------------------
// Edge kernel: warp owns 32 edges.
// Phase 1 (lane = edge): coalesced index loads, float4 grid gathers, d2 -> smem.
// Phase 2 (8 lanes per edge, 4 channels per lane): 4 edges retired per iter
//   via ONE red.global.add.v4.f32 warp-instruction (sm_90+ vector reduction).
// ---------------------------------------------------------------------------
__global__ void edge_kernel(const int* __restrict__ es,
                            const int* __restrict__ ed,
                            const float* __restrict__ bw) {
    __shared__ float4 stage[8][32];                  // 8 warps/block
    int tid  = blockIdx.x * blockDim.x + threadIdx.x;
    int lane = threadIdx.x & 31;
    int w    = threadIdx.x >> 5;

    // ---- phase 1: lane = edge ----
    int e   = tid;                                   // grid sized to ETOT
    int b   = e >> 19;                               // NN*KK = 2^19
    int off = b << 15;                               // b * NN
    int s   = __ldg(es + e) + off;
    int d   = __ldg(ed + e) + off;

    float4 gs = g_grid4[s];
    float4 gd = g_grid4[d];
    float dx = gs.x - gd.x;
    float dy = gs.y - gd.y;
    float dz = gs.z - gd.z;
    float d2 = dx * dx + dy * dy + dz * dz;

    stage[w][lane] = make_float4(__int_as_float(s * HH),
                                 __int_as_float(d * HH), d2, 0.f);
    __syncwarp();

    // ---- phase 2: grp = which edge of the quad, sub*4 = first channel ----
    int grp = lane >> 3;                             // 0..3
    int c0  = (lane & 7) * 4;                        // 0,4,...,28

    float4 bw4 = *reinterpret_cast<const float4*>(bw + c0);
    const float L2E = -1.4426950408889634f;          // -log2(e)
    float nb0 = bw4.x * L2E;
    float nb1 = bw4.y * L2E;
    float nb2 = bw4.z * L2E;
    float nb3 = bw4.w * L2E;

#pragma unroll
    for (int i = 0; i < 32; i += 4) {
        float4 p  = stage[w][i + grp];               // 4-way LDS.128 broadcast
        int   si  = __float_as_int(p.x);
        int   di  = __float_as_int(p.y);
        float d2i = p.z;

        // 4 fp16 m values: 8B aligned load
        unsigned long long mraw =
            *reinterpret_cast<const unsigned long long*>(g_mh + si + c0);
        __half2 hA = *reinterpret_cast<__half2*>(&mraw);
        __half2 hB = *(reinterpret_cast<__half2*>(&mraw) + 1);
        float2 fA = __half22float2(hA);
        float2 fB = __half22float2(hB);

        float e0, e1, e2, e3;
        asm("ex2.approx.f32 %0, %1;" : "=f"(e0) : "f"(nb0 * d2i));
        asm("ex2.approx.f32 %0, %1;" : "=f"(e1) : "f"(nb1 * d2i));
        asm("ex2.approx.f32 %0, %1;" : "=f"(e2) : "f"(nb2 * d2i));
        asm("ex2.approx.f32 %0, %1;" : "=f"(e3) : "f"(nb3 * d2i));

        float v0 = fA.x * e0;
        float v1 = fA.y * e1;
        float v2 = fB.x * e2;
        float v3 = fB.y * e3;

        // one vector reduction: 16B per lane, 16B-aligned (di%32==0, c0%4==0)
        asm volatile("red.global.add.v4.f32 [%0], {%1, %2, %3, %4};"
                     :: "l"(g_acc + di + c0),
                        "f"(v0), "f"(v1), "f"(v2), "f"(v3)
                     : "memory");
    }
}

// ---------------------------------------------------------------------------
// gemm2: out[b,o,n] = sum_h W2[o,h]*acc[g,h] + b2[o]   [unchanged, passing]
// ---------------------------------------------------------------------------
__global__ void gemm2_kernel(float* __restrict__ out) {
    int g = blockIdx.x * blockDim.x + threadIdx.x;
    int b = g >> 15;
    int n = g & (NN - 1);

    float a[HH];
    const float4* av = reinterpret_cast<const float4*>(g_acc + (size_t)g * HH);
#pragma unroll
    for (int i = 0; i < HH / 4; i++) {
        float4 v = av[i];
        a[4 * i + 0] = v.x;
        a[4 * i + 1] = v.y;
        a[4 * i + 2] = v.z;
        a[4 * i + 3] = v.w;
    }

    float* ob = out + (size_t)b * COUT * NN + n;
#pragma unroll
    for (int o = 0; o < COUT; o++) {
        float s = cb2[o];
#pragma unroll
        for (int h = 0; h < HH; h++)
            s += cW2[o * HH + h] * a[h];             // LDCU + FFMA
        ob[(size_t)o * NN] = s;
    }
}

// ---------------------------------------------------------------------------
// Launcher
// inputs: 0:x 1:grid 2:grid_weight 3:edge_src 4:edge_dst 5:W1 6:b1 7:W2 8:b2 9:baseweight
// ---------------------------------------------------------------------------
extern "C" void kernel_launch(void* const* d_in, const int* in_sizes, int n_in,
                              void* d_out, int out_size) {
    const float* x    = (const float*)d_in[0];
    const float* grid = (const float*)d_in[1];
    const float* gw   = (const float*)d_in[2];
    const int*   es   = (const int*)d_in[3];
    const int*   ed   = (const int*)d_in[4];
    const float* W1   = (const float*)d_in[5];
    const float* b1   = (const float*)d_in[6];
    const float* W2   = (const float*)d_in[7];
    const float* b2   = (const float*)d_in[8];
    const float* bw   = (const float*)d_in[9];
    float* out = (float*)d_out;

    // Stage small weights into constant memory (D2D, graph-capturable)
    cudaMemcpyToSymbolAsync(cW1, W1, HH * CIN * sizeof(float), 0,
                            cudaMemcpyDeviceToDevice, 0);
    cudaMemcpyToSymbolAsync(cb1, b1, HH * sizeof(float), 0,
                            cudaMemcpyDeviceToDevice, 0);
    cudaMemcpyToSymbolAsync(cbw, bw, HH * sizeof(float), 0,
                            cudaMemcpyDeviceToDevice, 0);
    cudaMemcpyToSymbolAsync(cW2, W2, COUT * HH * sizeof(float), 0,
                            cudaMemcpyDeviceToDevice, 0);
    cudaMemcpyToSymbolAsync(cb2, b2, COUT * sizeof(float), 0,
                            cudaMemcpyDeviceToDevice, 0);

    // 1) fused fc1 + gauss-norm + grid_weight -> g_mh ; zero acc ; pack grid
    gemm1_kernel<<<(GTOT / 2) / 256, 256>>>(x, gw, grid);

    // 2) edge scatter: 32 edges per warp, two-phase, RED.v4
    edge_kernel<<<ETOT / 256, 256>>>(es, ed, bw);

    // 3) fc2 + transpose to (B, COUT, N)
    gemm2_kernel<<<GTOT / 256, 256>>>(out);
}